// round 5
// baseline (speedup 1.0000x reference)
#include <cuda_runtime.h>
#include <cfloat>

// Caffe-style RoI max pooling matching the XLA-executed JAX reference.
//   x:    [2, 256, 64, 64] f32, rois: [2048, 5] f32 -> out: [2048, 256, 7, 7] f32
//
// Numerics (bit-exact to XLA): bin = roi_dim * RN(1/7) (0x3E124925),
// rintf for jnp.round, floorf/ceilf exact, __fmul_rn everywhere.
//
// Strategy: one block per roi. The roi's bounding box (<= 37x37 for this
// data distribution: roi dims <= 36, ceil(7*RN(d*rc7)) <= d+1) is staged
// into shared memory 8 channels at a time with coalesced row loads; the
// 8*49 bin maxes are then computed from shared (conflict-free pitches).

#define PH 7
#define PW 7
#define SCALE 0.0625f
#define NTHR 256
#define NWARPS 8
#define CH 8
#define WPITCH 38
#define CSTRIDE (38 * 38 + 1)   // 1445 floats per channel; 1445 % 32 = 5

__global__ void __launch_bounds__(NTHR, 4)
roipool_tile_kernel(const float* __restrict__ x,
                    const float* __restrict__ rois,
                    float* __restrict__ out)
{
    __shared__ float tile[CH * CSTRIDE];          // 46.2 KB
    __shared__ int s_ws[PW], s_we[PW], s_hs[PH], s_he[PH];
    __shared__ int s_wsl[PW], s_wel[PW], s_hsl[PH], s_hel[PH];
    __shared__ int s_b, s_r0, s_c0, s_hspan, s_wspan;

    const int H = 64, W = 64;
    const int r = blockIdx.x;
    const float* roi = rois + (size_t)r * 5;

    if (threadIdx.x == 0) {
        const int xs = (int)rintf(__fmul_rn(roi[1], SCALE));
        const int ys = (int)rintf(__fmul_rn(roi[2], SCALE));
        const int xe = (int)rintf(__fmul_rn(roi[3], SCALE));
        const int ye = (int)rintf(__fmul_rn(roi[4], SCALE));
        const float roi_w = (float)max(xe - xs + 1, 1);
        const float roi_h = (float)max(ye - ys + 1, 1);
        const float rc7 = __uint_as_float(0x3E124925u);   // RN(1/7), XLA's rewrite
        const float bw = __fmul_rn(roi_w, rc7);
        const float bh = __fmul_rn(roi_h, rc7);
        #pragma unroll
        for (int p = 0; p < 7; ++p) {
            const float pf = (float)p;
            s_ws[p] = min(max((int)floorf(__fmul_rn(pf, bw)) + xs, 0), W);
            s_we[p] = min(max((int)ceilf(__fmul_rn(pf + 1.0f, bw)) + xs, 0), W);
            s_hs[p] = min(max((int)floorf(__fmul_rn(pf, bh)) + ys, 0), H);
            s_he[p] = min(max((int)ceilf(__fmul_rn(pf + 1.0f, bh)) + ys, 0), H);
        }
        const int c0 = s_ws[0], r0 = s_hs[0];
        s_c0 = c0; s_r0 = r0;
        s_wspan = s_we[6] - c0;          // <= 37 (fits WPITCH=38)
        s_hspan = s_he[6] - r0;          // <= 37
        #pragma unroll
        for (int p = 0; p < 7; ++p) {
            s_wsl[p] = s_ws[p] - c0;  s_wel[p] = s_we[p] - c0;
            s_hsl[p] = s_hs[p] - r0;  s_hel[p] = s_he[p] - r0;
        }
        s_b = (int)roi[0];
    }
    __syncthreads();

    const int wid  = threadIdx.x >> 5;
    const int lane = threadIdx.x & 31;
    const int b = s_b, r0 = s_r0, c0 = s_c0;
    const int hspan = s_hspan, wspan = s_wspan;
    const float* img = x + (size_t)b * 256 * 4096;
    float* out_r = out + (size_t)r * 12544;

    for (int chunk = 0; chunk < 256 / CH; ++chunk) {
        const int cbase = chunk * CH;

        // ---- Phase A: coalesced staging of the bbox for CH channels ----
        #pragma unroll
        for (int cc = 0; cc < CH; ++cc) {
            const float* src = img + (size_t)(cbase + cc) * 4096 + r0 * 64 + c0;
            float* dst = tile + cc * CSTRIDE;
            for (int i = wid; i < hspan; i += NWARPS) {
                const float* srow = src + i * 64;
                float* drow = dst + i * WPITCH;
                if (lane < wspan) drow[lane] = __ldg(srow + lane);
                const int j2 = lane + 32;
                if (j2 < wspan) drow[j2] = __ldg(srow + j2);
            }
        }
        __syncthreads();

        // ---- Phase B: bin maxes from shared ----
        for (int t = threadIdx.x; t < CH * 49; t += NTHR) {
            const int pw = t % 7;
            const int u  = t / 7;
            const int ph = u % 7;
            const int cc = u / 7;

            const int ws = s_wsl[pw], we = s_wel[pw];
            const int hs = s_hsl[ph], he = s_hel[ph];

            float m = -FLT_MAX;
            const float* tp = tile + cc * CSTRIDE;
            for (int i = hs; i < he; ++i) {
                const float* rowp = tp + i * WPITCH;
                #pragma unroll 4
                for (int w = ws; w < we; ++w)
                    m = fmaxf(m, rowp[w]);
            }
            out_r[chunk * (CH * 49) + t] = (he <= hs || we <= ws) ? 0.0f : m;
        }
        __syncthreads();
    }
}

extern "C" void kernel_launch(void* const* d_in, const int* in_sizes, int n_in,
                              void* d_out, int out_size)
{
    const float* x    = (const float*)d_in[0];
    const float* rois = (const float*)d_in[1];
    float* out        = (float*)d_out;
    const int R = in_sizes[1] / 5;

    roipool_tile_kernel<<<R, NTHR>>>(x, rois, out);
}

// round 6
// speedup vs baseline: 5.7643x; 5.7643x over previous
#include <cuda_runtime.h>
#include <cfloat>

// Caffe-style RoI max pooling, bit-exact to the XLA-executed JAX reference.
//   x: [2,256,64,64] f32, rois: [2048,5] f32 -> out: [2048,256,7,7] f32
// Numerics: bin = roi_dim * RN(1/7) (0x3E124925) — XLA rewrites const-division
// into reciprocal multiply; rintf == jnp.round; __fmul_rn for boundary muls.
//
// Plan:
//   K1: transpose x -> xt[b][h][w][c] (channels-last), 8 MB device scratch.
//   K2: one block per roi, one bin per warp. Warp-uniform bounds (no
//       divergence); each lane float4-loads 4 contiguous channels -> fully
//       coalesced 512B warp transactions. Results staged in shared [C][49],
//       then written out linearly (coalesced 103 MB store).

#define PH 7
#define PW 7
#define SCALE 0.0625f
#define NTHR 256
#define PITCH 50                       // sbin row pitch (49 bins + pad)

__device__ float g_xt[2 * 64 * 64 * 256];   // [b][h][w][c]

// ---- K1: [b][c][hw] -> [b][hw][c] tiled transpose ----
__global__ void __launch_bounds__(256)
transpose_kernel(const float* __restrict__ x)
{
    __shared__ float t[32][33];
    const int tx = threadIdx.x & 31;
    const int ty = threadIdx.x >> 5;        // 0..7
    const int hw0 = blockIdx.x * 32;        // 128 blocks over HW=4096
    const int c0  = blockIdx.y * 32;        // 8 blocks over C=256
    const int b   = blockIdx.z;
    const float* src = x + (size_t)b * 256 * 4096;
    float* dst = g_xt + (size_t)b * 4096 * 256;

    #pragma unroll
    for (int i = 0; i < 32; i += 8)
        t[ty + i][tx] = src[(size_t)(c0 + ty + i) * 4096 + hw0 + tx];
    __syncthreads();
    #pragma unroll
    for (int i = 0; i < 32; i += 8)
        dst[(size_t)(hw0 + ty + i) * 256 + c0 + tx] = t[tx][ty + i];
}

__device__ __forceinline__ float4 fmax4(float4 a, float4 b) {
    return make_float4(fmaxf(a.x, b.x), fmaxf(a.y, b.y),
                       fmaxf(a.z, b.z), fmaxf(a.w, b.w));
}

// ---- K2: pooling, one block per roi ----
__global__ void __launch_bounds__(NTHR, 4)
roipool_cl_kernel(const float* __restrict__ rois,
                  float* __restrict__ out)
{
    __shared__ float sbin[256 * PITCH];     // 51.2 KB: [channel][bin]
    __shared__ int s_ws[PW], s_we[PW], s_hs[PH], s_he[PH];
    __shared__ int s_b;

    const int H = 64, W = 64;
    const int r = blockIdx.x;
    const float* roi = rois + (size_t)r * 5;

    if (threadIdx.x == 0) {
        const int xs = (int)rintf(__fmul_rn(roi[1], SCALE));
        const int ys = (int)rintf(__fmul_rn(roi[2], SCALE));
        const int xe = (int)rintf(__fmul_rn(roi[3], SCALE));
        const int ye = (int)rintf(__fmul_rn(roi[4], SCALE));
        const float roi_w = (float)max(xe - xs + 1, 1);
        const float roi_h = (float)max(ye - ys + 1, 1);
        const float rc7 = __uint_as_float(0x3E124925u);   // RN(1/7): XLA rewrite
        const float bw = __fmul_rn(roi_w, rc7);
        const float bh = __fmul_rn(roi_h, rc7);
        #pragma unroll
        for (int p = 0; p < 7; ++p) {
            const float pf = (float)p;
            s_ws[p] = min(max((int)floorf(__fmul_rn(pf, bw)) + xs, 0), W);
            s_we[p] = min(max((int)ceilf(__fmul_rn(pf + 1.0f, bw)) + xs, 0), W);
            s_hs[p] = min(max((int)floorf(__fmul_rn(pf, bh)) + ys, 0), H);
            s_he[p] = min(max((int)ceilf(__fmul_rn(pf + 1.0f, bh)) + ys, 0), H);
        }
        s_b = (int)roi[0];
    }
    __syncthreads();

    const int wid  = threadIdx.x >> 5;      // 8 warps
    const int lane = threadIdx.x & 31;
    const float* xb = g_xt + (size_t)s_b * 4096 * 256;

    // Phase 1: one bin per warp; lanes cover channels [4*lane, 4*lane+4) and
    // [128+4*lane, 128+4*lane+4) as two float4 accumulators.
    for (int bin = wid; bin < 49; bin += 8) {
        const int ph = bin / 7, pw = bin % 7;
        const int hs = s_hs[ph], he = s_he[ph];
        const int ws = s_ws[pw], we = s_we[pw];

        float4 m0 = make_float4(-FLT_MAX, -FLT_MAX, -FLT_MAX, -FLT_MAX);
        float4 m1 = m0;

        for (int h = hs; h < he; ++h) {
            const float* p = xb + ((size_t)(h * 64 + ws)) * 256 + 4 * lane;
            for (int w = ws; w < we; ++w, p += 256) {
                const float4 a = *(const float4*)p;
                const float4 c = *(const float4*)(p + 128);
                m0 = fmax4(m0, a);
                m1 = fmax4(m1, c);
            }
        }
        const bool empty = (he <= hs) || (we <= ws);
        if (empty) { m0 = make_float4(0,0,0,0); m1 = m0; }

        const int c0 = 4 * lane;
        sbin[(c0 + 0) * PITCH + bin] = m0.x;
        sbin[(c0 + 1) * PITCH + bin] = m0.y;
        sbin[(c0 + 2) * PITCH + bin] = m0.z;
        sbin[(c0 + 3) * PITCH + bin] = m0.w;
        sbin[(c0 + 128) * PITCH + bin] = m1.x;
        sbin[(c0 + 129) * PITCH + bin] = m1.y;
        sbin[(c0 + 130) * PITCH + bin] = m1.z;
        sbin[(c0 + 131) * PITCH + bin] = m1.w;
    }
    __syncthreads();

    // Phase 2: coalesced linear store of the roi's 12544 outputs.
    float* out_r = out + (size_t)r * 12544;
    #pragma unroll 7
    for (int i = threadIdx.x; i < 12544; i += NTHR) {
        const int c = i / 49;
        const int bin = i - c * 49;
        out_r[i] = sbin[c * PITCH + bin];
    }
}

extern "C" void kernel_launch(void* const* d_in, const int* in_sizes, int n_in,
                              void* d_out, int out_size)
{
    const float* x    = (const float*)d_in[0];
    const float* rois = (const float*)d_in[1];
    float* out        = (float*)d_out;
    const int R = in_sizes[1] / 5;

    dim3 tg(128, 8, 2);
    transpose_kernel<<<tg, 256>>>(x);
    roipool_cl_kernel<<<R, NTHR>>>(rois, out);
}

// round 7
// speedup vs baseline: 6.6845x; 1.1596x over previous
#include <cuda_runtime.h>
#include <cfloat>

// Caffe-style RoI max pooling, bit-exact to the XLA-executed JAX reference.
//   x: [2,256,64,64] f32, rois: [2048,5] f32 -> out: [2048,256,7,7] f32
// Numerics: bin = roi_dim * RN(1/7) (0x3E124925) — XLA rewrites const-division
// into reciprocal multiply; rintf == jnp.round; __fmul_rn for boundary muls.
//
// K1: transpose x -> xt[b][h][w][c] (channels-last) in a device scratch array.
// K2: one block per roi, one (bin) task per warp; warp-uniform bounds; each
//     lane float4-loads channels [4L,4L+4) and [128+4L,128+4L+4) -> two
//     coalesced LDG.128 per cell. Bin results staged in sbin[bin][c]
//     (pitch 260 -> conflict-free STS.128), then written out linearly.

#define PH 7
#define PW 7
#define SCALE 0.0625f
#define NTHR 256
#define SPITCH 260                     // floats per bin row; 260*4=1040B, 16B-aligned

__device__ float g_xt[2 * 64 * 64 * 256];   // [b][h][w][c]

// ---- K1: [b][c][hw] -> [b][hw][c] tiled transpose ----
__global__ void __launch_bounds__(256)
transpose_kernel(const float* __restrict__ x)
{
    __shared__ float t[32][33];
    const int tx = threadIdx.x & 31;
    const int ty = threadIdx.x >> 5;        // 0..7
    const int hw0 = blockIdx.x * 32;        // 128 blocks over HW=4096
    const int c0  = blockIdx.y * 32;        // 8 blocks over C=256
    const int b   = blockIdx.z;
    const float* src = x + (size_t)b * 256 * 4096;
    float* dst = g_xt + (size_t)b * 4096 * 256;

    #pragma unroll
    for (int i = 0; i < 32; i += 8)
        t[ty + i][tx] = src[(size_t)(c0 + ty + i) * 4096 + hw0 + tx];
    __syncthreads();
    #pragma unroll
    for (int i = 0; i < 32; i += 8)
        dst[(size_t)(hw0 + ty + i) * 256 + c0 + tx] = t[tx][ty + i];
}

__device__ __forceinline__ float4 fmax4(float4 a, float4 b) {
    return make_float4(fmaxf(a.x, b.x), fmaxf(a.y, b.y),
                       fmaxf(a.z, b.z), fmaxf(a.w, b.w));
}

// ---- K2: pooling, one block per roi ----
__global__ void __launch_bounds__(NTHR, 4)
roipool_cl_kernel(const float* __restrict__ rois,
                  float* __restrict__ out)
{
    __shared__ float sbin[49 * SPITCH];     // 50.96 KB: [bin][channel]
    __shared__ int s_ws[PW], s_we[PW], s_hs[PH], s_he[PH];
    __shared__ int s_b;

    const int H = 64, W = 64;
    const int r = blockIdx.x;
    const float* roi = rois + (size_t)r * 5;

    if (threadIdx.x == 0) {
        const int xs = (int)rintf(__fmul_rn(roi[1], SCALE));
        const int ys = (int)rintf(__fmul_rn(roi[2], SCALE));
        const int xe = (int)rintf(__fmul_rn(roi[3], SCALE));
        const int ye = (int)rintf(__fmul_rn(roi[4], SCALE));
        const float roi_w = (float)max(xe - xs + 1, 1);
        const float roi_h = (float)max(ye - ys + 1, 1);
        const float rc7 = __uint_as_float(0x3E124925u);   // RN(1/7): XLA rewrite
        const float bw = __fmul_rn(roi_w, rc7);
        const float bh = __fmul_rn(roi_h, rc7);
        #pragma unroll
        for (int p = 0; p < 7; ++p) {
            const float pf = (float)p;
            s_ws[p] = min(max((int)floorf(__fmul_rn(pf, bw)) + xs, 0), W);
            s_we[p] = min(max((int)ceilf(__fmul_rn(pf + 1.0f, bw)) + xs, 0), W);
            s_hs[p] = min(max((int)floorf(__fmul_rn(pf, bh)) + ys, 0), H);
            s_he[p] = min(max((int)ceilf(__fmul_rn(pf + 1.0f, bh)) + ys, 0), H);
        }
        s_b = (int)roi[0];
    }
    __syncthreads();

    const int wid  = threadIdx.x >> 5;      // 8 warps
    const int lane = threadIdx.x & 31;
    const float* xb = g_xt + (size_t)s_b * 4096 * 256;

    // Phase 1: one bin per warp; lanes cover channels [4L,4L+4) and
    // [128+4L,128+4L+4). Conflict-free STS.128 into sbin[bin][*].
    for (int bin = wid; bin < 49; bin += 8) {
        const int ph = bin / 7, pw = bin % 7;
        const int hs = s_hs[ph], he = s_he[ph];
        const int ws = s_ws[pw], we = s_we[pw];

        float4 m0 = make_float4(-FLT_MAX, -FLT_MAX, -FLT_MAX, -FLT_MAX);
        float4 m1 = m0;

        for (int h = hs; h < he; ++h) {
            const float* p = xb + ((size_t)(h * 64 + ws)) * 256 + 4 * lane;
            for (int w = ws; w < we; ++w, p += 256) {
                const float4 a = *(const float4*)p;
                const float4 c = *(const float4*)(p + 128);
                m0 = fmax4(m0, a);
                m1 = fmax4(m1, c);
            }
        }
        if ((he <= hs) || (we <= ws)) {
            m0 = make_float4(0.0f, 0.0f, 0.0f, 0.0f);
            m1 = m0;
        }

        float* s = sbin + bin * SPITCH + 4 * lane;
        *(float4*)s = m0;
        *(float4*)(s + 128) = m1;
    }
    __syncthreads();

    // Phase 2: coalesced linear store of the roi's 12544 outputs.
    // i = c*49 + bin; maintain (c, bin) incrementally (256 = 5*49 + 11).
    float* out_r = out + (size_t)r * 12544;
    {
        int i = threadIdx.x;
        int c = i / 49;
        int bin = i - c * 49;
        #pragma unroll 1
        for (int k = 0; k < 49; ++k) {
            out_r[i] = sbin[bin * SPITCH + c];
            i += NTHR;
            c += 5; bin += 11;
            if (bin >= 49) { bin -= 49; ++c; }
        }
    }
}

extern "C" void kernel_launch(void* const* d_in, const int* in_sizes, int n_in,
                              void* d_out, int out_size)
{
    const float* x    = (const float*)d_in[0];
    const float* rois = (const float*)d_in[1];
    float* out        = (float*)d_out;
    const int R = in_sizes[1] / 5;

    dim3 tg(128, 8, 2);
    transpose_kernel<<<tg, 256>>>(x);
    roipool_cl_kernel<<<R, NTHR>>>(rois, out);
}